// round 1
// baseline (speedup 1.0000x reference)
#include <cuda_runtime.h>
#include <math.h>

#define NN     50000
#define EE     600000
#define GG     256
#define HID    128
#define EDIM   16
#define EH     64
#define NL     4
#define MINF   200
#define MH     256
#define MOUT   128
#define PH     512
#define PIN    (HID + MOUT)

// ---------------- scratch (static device globals; no runtime alloc) -------
__device__ float g_w[NL * EE];
__device__ float g_deg[NL * NN];
__device__ float g_dinv[NL * NN];
__device__ float g_h[NN * HID];
__device__ float g_hl[NN * HID];
__device__ float g_out[NN * HID];
__device__ float g_pool[GG * HID];
__device__ float g_cnt[GG];
__device__ float g_t0[GG * MH];
__device__ float g_t1[GG * MH];
__device__ float g_cat[GG * PIN];
__device__ float g_p0[GG * PH];
__device__ float g_p1[GG * PH];

// ---------------- edge MLP (all 4 layers fused) ---------------------------
__global__ __launch_bounds__(256) void edge_mlp_all(
    const float* __restrict__ ea, const float* __restrict__ mW1,
    const float* __restrict__ mb1, const float* __restrict__ mW2,
    const float* __restrict__ mb2)
{
    __shared__ float sW1t[NL][EH * EDIM];   // transposed: [l][j][k]
    __shared__ float sb1[NL][EH];
    __shared__ float sW2[NL][EH];
    __shared__ float sb2[NL];
    int t = threadIdx.x;
    for (int i = t; i < NL * EDIM * EH; i += 256) {
        int l = i / (EDIM * EH);
        int rem = i % (EDIM * EH);
        int k = rem / EH, j = rem % EH;
        sW1t[l][j * EDIM + k] = mW1[i];
    }
    for (int i = t; i < NL * EH; i += 256) {
        sb1[i / EH][i % EH] = mb1[i];
        sW2[i / EH][i % EH] = mW2[i];
    }
    if (t < NL) sb2[t] = mb2[t];
    __syncthreads();

    int e = blockIdx.x * 256 + t;
    if (e >= EE) return;
    float a[EDIM];
    const float4* eap = (const float4*)(ea + (size_t)e * EDIM);
#pragma unroll
    for (int q = 0; q < 4; q++) {
        float4 v = eap[q];
        a[q * 4 + 0] = v.x; a[q * 4 + 1] = v.y; a[q * 4 + 2] = v.z; a[q * 4 + 3] = v.w;
    }
#pragma unroll 1
    for (int l = 0; l < NL; l++) {
        float acc = sb2[l];
#pragma unroll 4
        for (int j = 0; j < EH; j++) {
            const float4* wp = (const float4*)&sW1t[l][j * EDIM];
            float s = sb1[l][j];
#pragma unroll
            for (int q = 0; q < 4; q++) {
                float4 w4 = wp[q];
                s = fmaf(a[q * 4 + 0], w4.x, s);
                s = fmaf(a[q * 4 + 1], w4.y, s);
                s = fmaf(a[q * 4 + 2], w4.z, s);
                s = fmaf(a[q * 4 + 3], w4.w, s);
            }
            acc = fmaf(fmaxf(s, 0.f), sW2[l][j], acc);
        }
        g_w[l * EE + e] = 1.f / (1.f + __expf(-acc));
    }
}

// ---------------- degree / norm -------------------------------------------
__global__ void deg_init()
{
    int i = blockIdx.x * blockDim.x + threadIdx.x;
    if (i < NL * NN) g_deg[i] = 1.0f;   // self loop
}

__global__ void deg_accum(const int* __restrict__ colp)
{
    int e = blockIdx.x * blockDim.x + threadIdx.x;
    if (e >= EE) return;
    int c = colp[e];
#pragma unroll
    for (int l = 0; l < NL; l++)
        atomicAdd(&g_deg[l * NN + c], g_w[l * EE + e]);
}

__global__ void dinv_kernel()
{
    int i = blockIdx.x * blockDim.x + threadIdx.x;
    if (i < NL * NN) {
        float d = g_deg[i];
        g_dinv[i] = (d > 0.f) ? rsqrtf(d) : 0.f;
    }
}

// ---------------- node matmul: 16 rows x 128 cols per block ---------------
__global__ __launch_bounds__(128) void node_mm(
    const float* __restrict__ in, const float* __restrict__ W,
    const float* __restrict__ bias, float* __restrict__ out,
    int do_relu, int has_bias)
{
    __shared__ float sin_t[128 * 20];   // [k][row], padded
    const int t = threadIdx.x;
    const int base = blockIdx.x * 16;
    for (int idx = t; idx < 16 * 128; idx += 128) {
        int row = idx >> 7, k = idx & 127;
        int grow = base + row;
        sin_t[k * 20 + row] = (grow < NN) ? in[(size_t)grow * HID + k] : 0.f;
    }
    __syncthreads();

    const int cx = t & 31;   // cols 4*cx..+3
    const int ry = t >> 5;   // rows 4*ry..+3 (warp-uniform -> LDS broadcast)
    float acc[4][4];
    float4 bv = has_bias ? *(const float4*)&bias[cx * 4] : make_float4(0.f, 0.f, 0.f, 0.f);
#pragma unroll
    for (int r = 0; r < 4; r++) {
        acc[r][0] = bv.x; acc[r][1] = bv.y; acc[r][2] = bv.z; acc[r][3] = bv.w;
    }
#pragma unroll 8
    for (int k = 0; k < 128; k++) {
        float4 wv = *(const float4*)&W[(size_t)k * HID + cx * 4];
        float4 iv = *(const float4*)&sin_t[k * 20 + ry * 4];
        acc[0][0] = fmaf(iv.x, wv.x, acc[0][0]); acc[0][1] = fmaf(iv.x, wv.y, acc[0][1]);
        acc[0][2] = fmaf(iv.x, wv.z, acc[0][2]); acc[0][3] = fmaf(iv.x, wv.w, acc[0][3]);
        acc[1][0] = fmaf(iv.y, wv.x, acc[1][0]); acc[1][1] = fmaf(iv.y, wv.y, acc[1][1]);
        acc[1][2] = fmaf(iv.y, wv.z, acc[1][2]); acc[1][3] = fmaf(iv.y, wv.w, acc[1][3]);
        acc[2][0] = fmaf(iv.z, wv.x, acc[2][0]); acc[2][1] = fmaf(iv.z, wv.y, acc[2][1]);
        acc[2][2] = fmaf(iv.z, wv.z, acc[2][2]); acc[2][3] = fmaf(iv.z, wv.w, acc[2][3]);
        acc[3][0] = fmaf(iv.w, wv.x, acc[3][0]); acc[3][1] = fmaf(iv.w, wv.y, acc[3][1]);
        acc[3][2] = fmaf(iv.w, wv.z, acc[3][2]); acc[3][3] = fmaf(iv.w, wv.w, acc[3][3]);
    }
#pragma unroll
    for (int r = 0; r < 4; r++) {
        int grow = base + ry * 4 + r;
        if (grow < NN) {
            float4 o = make_float4(acc[r][0], acc[r][1], acc[r][2], acc[r][3]);
            if (do_relu) {
                o.x = fmaxf(o.x, 0.f); o.y = fmaxf(o.y, 0.f);
                o.z = fmaxf(o.z, 0.f); o.w = fmaxf(o.w, 0.f);
            }
            *(float4*)&out[(size_t)grow * HID + cx * 4] = o;
        }
    }
}

// ---------------- self-loop init + bias -----------------------------------
__global__ void self_init(const float* __restrict__ dinv,
                          const float* __restrict__ bias)
{
    int idx = blockIdx.x * blockDim.x + threadIdx.x;
    if (idx >= NN * HID) return;
    int i = idx >> 7, j = idx & 127;
    float d = dinv[i];
    g_out[idx] = d * d * g_hl[idx] + bias[j];
}

// ---------------- edge scatter: 32 lanes (float4 each) per edge -----------
__global__ __launch_bounds__(256) void scatter(
    const int* __restrict__ rowp, const int* __restrict__ colp,
    const float* __restrict__ w, const float* __restrict__ dinv)
{
    int gid = blockIdx.x * 256 + threadIdx.x;
    int e = gid >> 5;
    int lane = gid & 31;
    if (e >= EE) return;
    int r = rowp[e], c = colp[e];
    float nrm = dinv[r] * w[e] * dinv[c];
    float4 v = ((const float4*)(g_hl + (size_t)r * HID))[lane];
    float* op = g_out + (size_t)c * HID + lane * 4;
    atomicAdd(op + 0, nrm * v.x);
    atomicAdd(op + 1, nrm * v.y);
    atomicAdd(op + 2, nrm * v.z);
    atomicAdd(op + 3, nrm * v.w);
}

// ---------------- mean pool -----------------------------------------------
__global__ void pool_init()
{
    int i = blockIdx.x * blockDim.x + threadIdx.x;
    if (i < GG * HID) g_pool[i] = 0.f;
    if (i < GG) g_cnt[i] = 0.f;
}

__global__ void pool_cnt(const int* __restrict__ batch)
{
    int i = blockIdx.x * blockDim.x + threadIdx.x;
    if (i < NN) atomicAdd(&g_cnt[batch[i]], 1.f);
}

__global__ void pool_accum(const int* __restrict__ batch)
{
    int idx = blockIdx.x * blockDim.x + threadIdx.x;
    if (idx >= NN * HID) return;
    int i = idx >> 7, j = idx & 127;
    atomicAdd(&g_pool[batch[i] * HID + j], g_h[idx]);
}

__global__ void pool_final()
{
    int idx = blockIdx.x * blockDim.x + threadIdx.x;
    if (idx < GG * HID) g_pool[idx] /= fmaxf(g_cnt[idx >> 7], 1.f);
}

// ---------------- small dense layers --------------------------------------
__global__ __launch_bounds__(256) void dense(
    const float* __restrict__ in, const float* __restrict__ W,
    const float* __restrict__ b, float* __restrict__ out,
    int K, int Nout, int do_relu)
{
    __shared__ float sin[512];
    int row = blockIdx.x;
    for (int i = threadIdx.x; i < K; i += blockDim.x) sin[i] = in[(size_t)row * K + i];
    __syncthreads();
    for (int j = threadIdx.x; j < Nout; j += blockDim.x) {
        float acc = b[j];
        for (int k = 0; k < K; k++) acc = fmaf(sin[k], W[(size_t)k * Nout + j], acc);
        out[(size_t)row * Nout + j] = do_relu ? fmaxf(acc, 0.f) : acc;
    }
}

__global__ void concat_kernel()
{
    int idx = blockIdx.x * blockDim.x + threadIdx.x;
    if (idx >= GG * PIN) return;
    int g = idx / PIN, j = idx % PIN;
    g_cat[idx] = (j < HID) ? g_pool[g * HID + j] : g_t1[g * MOUT + (j - HID)];
}

__global__ __launch_bounds__(128) void final_out(
    const float* __restrict__ W, const float* __restrict__ b,
    float* __restrict__ out)
{
    int g = blockIdx.x, t = threadIdx.x;
    float acc = 0.f;
    for (int k = t; k < PH; k += 128) acc = fmaf(g_p1[(size_t)g * PH + k], W[k], acc);
#pragma unroll
    for (int off = 16; off; off >>= 1) acc += __shfl_xor_sync(0xFFFFFFFFu, acc, off);
    __shared__ float s[4];
    if ((t & 31) == 0) s[t >> 5] = acc;
    __syncthreads();
    if (t == 0) out[g] = s[0] + s[1] + s[2] + s[3] + b[0];
}

// ---------------- launch --------------------------------------------------
extern "C" void kernel_launch(void* const* d_in, const int* in_sizes, int n_in,
                              void* d_out, int out_size)
{
    const float* x     = (const float*)d_in[0];
    const int*   ei    = (const int*)d_in[1];
    const float* ea    = (const float*)d_in[2];
    const int*   batch = (const int*)d_in[3];
    const float* mol   = (const float*)d_in[4];
    const float* clinW = (const float*)d_in[5];
    const float* cmW1  = (const float*)d_in[6];
    const float* cmb1  = (const float*)d_in[7];
    const float* cmW2  = (const float*)d_in[8];
    const float* cmb2  = (const float*)d_in[9];
    const float* cbias = (const float*)d_in[10];
    const float* gcnW  = (const float*)d_in[11];
    const float* gcnb  = (const float*)d_in[12];
    const float* mW0 = (const float*)d_in[13]; const float* mb0 = (const float*)d_in[14];
    const float* mW1 = (const float*)d_in[15]; const float* mb1 = (const float*)d_in[16];
    const float* mW2 = (const float*)d_in[17]; const float* mb2 = (const float*)d_in[18];
    const float* mW3 = (const float*)d_in[19]; const float* mb3 = (const float*)d_in[20];
    const float* pW0 = (const float*)d_in[21]; const float* pb0 = (const float*)d_in[22];
    const float* pW1 = (const float*)d_in[23]; const float* pb1 = (const float*)d_in[24];
    const float* oW  = (const float*)d_in[25]; const float* ob  = (const float*)d_in[26];
    float* out = (float*)d_out;

    const int* rowp = ei;
    const int* colp = ei + EE;

    static float *h_ptr = nullptr, *hl_ptr = nullptr, *out_ptr = nullptr;
    static float *w_ptr = nullptr, *dinv_ptr = nullptr;
    static float *pool_p = nullptr, *t0_p = nullptr, *t1_p = nullptr;
    static float *cat_p = nullptr, *p0_p = nullptr, *p1_p = nullptr;
    if (!h_ptr) {
        cudaGetSymbolAddress((void**)&h_ptr, g_h);
        cudaGetSymbolAddress((void**)&hl_ptr, g_hl);
        cudaGetSymbolAddress((void**)&out_ptr, g_out);
        cudaGetSymbolAddress((void**)&w_ptr, g_w);
        cudaGetSymbolAddress((void**)&dinv_ptr, g_dinv);
        cudaGetSymbolAddress((void**)&pool_p, g_pool);
        cudaGetSymbolAddress((void**)&t0_p, g_t0);
        cudaGetSymbolAddress((void**)&t1_p, g_t1);
        cudaGetSymbolAddress((void**)&cat_p, g_cat);
        cudaGetSymbolAddress((void**)&p0_p, g_p0);
        cudaGetSymbolAddress((void**)&p1_p, g_p1);
    }

    // edge gates + norms for all layers up-front
    edge_mlp_all<<<(EE + 255) / 256, 256>>>(ea, cmW1, cmb1, cmW2, cmb2);
    deg_init<<<(NL * NN + 255) / 256, 256>>>();
    deg_accum<<<(EE + 255) / 256, 256>>>(colp);
    dinv_kernel<<<(NL * NN + 255) / 256, 256>>>();

    const int mm_grid = (NN + 15) / 16;
    for (int l = 0; l < NL; l++) {
        const float* hin = (l == 0) ? x : h_ptr;
        node_mm<<<mm_grid, 128>>>(hin, clinW + (size_t)l * HID * HID,
                                  (const float*)nullptr, hl_ptr, 0, 0);
        self_init<<<(NN * HID + 255) / 256, 256>>>(dinv_ptr + (size_t)l * NN,
                                                   cbias + (size_t)l * HID);
        scatter<<<(EE * 32 + 255) / 256, 256>>>(rowp, colp,
                                                w_ptr + (size_t)l * EE,
                                                dinv_ptr + (size_t)l * NN);
        node_mm<<<mm_grid, 128>>>(out_ptr, gcnW + (size_t)l * HID * HID,
                                  gcnb + (size_t)l * HID, h_ptr, 1, 1);
    }

    pool_init<<<(GG * HID + 255) / 256, 256>>>();
    pool_cnt<<<(NN + 255) / 256, 256>>>(batch);
    pool_accum<<<(NN * HID + 255) / 256, 256>>>(batch);
    pool_final<<<(GG * HID + 255) / 256, 256>>>();

    dense<<<GG, 256>>>(mol,  mW0, mb0, t0_p, MINF, MH,   1);
    dense<<<GG, 256>>>(t0_p, mW1, mb1, t1_p, MH,   MH,   1);
    dense<<<GG, 256>>>(t1_p, mW2, mb2, t0_p, MH,   MH,   1);
    dense<<<GG, 256>>>(t0_p, mW3, mb3, t1_p, MH,   MOUT, 1);

    concat_kernel<<<(GG * PIN + 255) / 256, 256>>>();

    dense<<<GG, 256>>>(cat_p, pW0, pb0, p0_p, PIN, PH, 1);
    dense<<<GG, 256>>>(p0_p,  pW1, pb1, p1_p, PH,  PH, 1);
    final_out<<<GG, 128>>>(oW, ob, out);
}